// round 8
// baseline (speedup 1.0000x reference)
#include <cuda_runtime.h>

#define NQ 10
#define NGEN 4
#define QD 6
#define BATCH 1024

typedef unsigned long long ull;

// ---- packed f32x2 helpers (re in lo, im in hi) ----
__device__ __forceinline__ ull pk(float lo, float hi) {
    ull r; asm("mov.b64 %0, {%1, %2};" : "=l"(r) : "f"(lo), "f"(hi)); return r;
}
__device__ __forceinline__ void upk(ull v, float& lo, float& hi) {
    asm("mov.b64 {%0, %1}, %2;" : "=f"(lo), "=f"(hi) : "l"(v));
}
__device__ __forceinline__ ull fma2(ull a, ull b, ull c) {
    ull d; asm("fma.rn.f32x2 %0, %1, %2, %3;" : "=l"(d) : "l"(a), "l"(b), "l"(c)); return d;
}

// One warp per (batch, gen) circuit. Amp index i (10 bits): lane = bits 9..5,
// register index r = bits 4..0. PennyLane wire q <-> bit (9-q).
__global__ void __launch_bounds__(64, 10) sim_kernel(const float* __restrict__ noise,
                                                     const float* __restrict__ qp,
                                                     float* __restrict__ out) {
    const unsigned FULL = 0xffffffffu;
    int gwarp = blockIdx.x * 2 + (threadIdx.x >> 5);
    int lane  = threadIdx.x & 31;
    int batch = gwarp >> 2;
    int gen   = gwarp & 3;

    ull S[32];  // packed (re, im) per amplitude (globally scaled by 1/G)

    // ---- in-warp angle prep for init ----
    // lanes 0..9: sincos(noise[batch,q]/2); lanes 16..25: sincos(w[gen,0,q]/2)
    float c_my = 0.f, s_my = 0.f;
    {
        float ang = 0.f;
        if (lane < NQ)                 ang = noise[batch * NQ + lane];
        else if (lane >= 16 && lane < 16 + NQ)
                                       ang = qp[(gen * QD + 0) * NQ + (lane - 16)];
        sincosf(0.5f * ang, &s_my, &c_my);
    }

    // Per-wire init vector: u = RX(n)RY(n)|0> = (C^2 - i S^2, CS - i CS),
    // then layer-0 RY(w):  v = RY(w) u   (exact, unscaled)
    auto wire_vec = [&](int q, float& v0r, float& v0i, float& v1r, float& v1i) {
        float C  = __shfl_sync(FULL, c_my, q);
        float Sn = __shfl_sync(FULL, s_my, q);
        float wc = __shfl_sync(FULL, c_my, 16 + q);
        float ws = __shfl_sync(FULL, s_my, 16 + q);
        float u0r = C * C, u0i = -Sn * Sn;
        float u1r = C * Sn, u1i = -(C * Sn);
        v0r = wc * u0r - ws * u1r;  v0i = wc * u0i - ws * u1i;
        v1r = ws * u0r + wc * u1r;  v1i = ws * u0i + wc * u1i;
    };

    // laneF = prod over wires 0..4 of v_w[bit], bit = (lane >> (4-w)) & 1
    float fr = 1.0f, fi = 0.0f;
    #pragma unroll
    for (int w = 0; w < 5; ++w) {
        float v0r, v0i, v1r, v1i;
        wire_vec(w, v0r, v0i, v1r, v1i);
        int bit = (lane >> (4 - w)) & 1;
        float pr = bit ? v1r : v0r;
        float pi = bit ? v1i : v0i;
        float nr = fr * pr - fi * pi;
        float ni = fr * pi + fi * pr;
        fr = nr; fi = ni;
    }

    // Build local 32-amp product table over wires 9..5 (bits 0..4 of r)
    S[0] = pk(fr, fi);
    #pragma unroll
    for (int k = 0; k < 5; ++k) {
        int w = 9 - k;
        int len = 1 << k;
        float v0r, v0i, v1r, v1i;
        wire_vec(w, v0r, v0i, v1r, v1i);
        #pragma unroll
        for (int r = 0; r < (1 << k); ++r) {
            float ar, ai; upk(S[r], ar, ai);
            S[r]       = pk(ar * v0r - ai * v0i, ar * v0i + ai * v0r);
            S[r + len] = pk(ar * v1r - ai * v1i, ar * v1i + ai * v1r);
        }
    }

    // CZ-chain sign mask: bit r of M = K(r) ^ p_lane ^ ((lane&1) & (r>>4))
    unsigned K = 0;
    #pragma unroll
    for (int r = 0; r < 32; ++r)
        K |= (unsigned)(__popc(r & (r >> 1)) & 1) << r;   // compile-time constant
    unsigned p_lane = __popc(lane & (lane >> 1)) & 1u;
    unsigned M = K ^ (p_lane ? 0xFFFFFFFFu : 0u) ^ ((lane & 1) ? 0xFFFF0000u : 0u);

    auto apply_cz = [&]() {
        #pragma unroll
        for (int r = 0; r < 32; ++r) {
            // sign bit of ((M>>r)&1) moved to bit31; xor both fp32 halves
            unsigned sg = (M << (31 - r)) & 0x80000000u;
            unsigned lo = (unsigned)S[r], hi = (unsigned)(S[r] >> 32);
            lo ^= sg; hi ^= sg;
            S[r] = ((ull)hi << 32) | lo;
        }
    };

    apply_cz();  // layer 0's CZ (layer-0 RY fused into init)

    float Gtot = 1.0f;  // product of all cos(theta/2) factored out of the gates

    #pragma unroll 1
    for (int l = 1; l < QD; ++l) {
        // lanes 0..9: this layer's cos, and t = tan(ang/2)
        float lc = 1.0f, lt = 0.0f;
        if (lane < NQ) {
            float ang = qp[(gen * QD + l) * NQ + lane];
            float ls;
            sincosf(0.5f * ang, &ls, &lc);
            lt = __fdividef(ls, lc);
        }
        // warp product of the 10 cos factors
        {
            float g = lc;
            #pragma unroll
            for (int o = 16; o > 0; o >>= 1)
                g *= __shfl_xor_sync(FULL, g, o);
            Gtot *= g;
        }

        // register-bit gates (wires 5..9): scaled RY = (a0 - t a1, t a0 + a1)
        #pragma unroll
        for (int q = 5; q < NQ; ++q) {
            const int m = 1 << (9 - q);
            float t = __shfl_sync(FULL, lt, q);
            ull tp = pk(t, t);
            ull tn = tp ^ 0x8000000080000000ull;
            #pragma unroll
            for (int r = 0; r < 32; ++r) {
                if (r & m) continue;
                int r1 = r | m;
                ull a0 = S[r], a1 = S[r1];
                S[r]  = fma2(tn, a1, a0);
                S[r1] = fma2(tp, a0, a1);
            }
        }

        // lane-bit gates (wires 0..4): S += (+-t) * partner
        #pragma unroll
        for (int q = 0; q < 5; ++q) {
            int lb = 4 - q;
            float t = __shfl_sync(FULL, lt, q);
            float tsgn = ((lane >> lb) & 1) ? t : -t;
            ull T = pk(tsgn, tsgn);
            #pragma unroll
            for (int r = 0; r < 32; ++r) {
                ull p = __shfl_xor_sync(FULL, S[r], 1 << lb);
                S[r] = fma2(T, p, S[r]);
            }
        }

        apply_cz();
    }

    // Expectations: <X_q> = G^2 * sum_i Re(conj(a_i) * a_{i ^ bit(9-q)})
    float G2 = Gtot * Gtot;
    float acc[NQ];
    #pragma unroll
    for (int q = 0; q < NQ; ++q) {
        float a = 0.0f;
        if (q < 5) {
            int lb = 4 - q;
            #pragma unroll
            for (int r = 0; r < 32; ++r) {
                ull p = __shfl_xor_sync(FULL, S[r], 1 << lb);
                float re, im, pre, pim;
                upk(S[r], re, im); upk(p, pre, pim);
                a = fmaf(re, pre, a);
                a = fmaf(im, pim, a);
            }
        } else {
            const int m = 1 << (9 - q);
            #pragma unroll
            for (int r = 0; r < 32; ++r) {
                float re, im, pre, pim;
                upk(S[r], re, im); upk(S[r ^ m], pre, pim);
                a = fmaf(re, pre, a);
                a = fmaf(im, pim, a);
            }
        }
        acc[q] = a * G2;
    }

    // packed pairwise butterfly reduction: 5 ull accs instead of 10 floats
    int obase = batch * (NGEN * NQ) + gen * NQ;
    #pragma unroll
    for (int k = 0; k < 5; ++k) {
        ull v = pk(acc[2 * k], acc[2 * k + 1]);
        #pragma unroll
        for (int o = 16; o > 0; o >>= 1) {
            ull p = __shfl_xor_sync(FULL, v, o);
            asm("add.rn.f32x2 %0, %1, %2;" : "=l"(v) : "l"(v), "l"(p));
        }
        if (lane == 0)
            *reinterpret_cast<float2*>(out + obase + 2 * k) =
                *reinterpret_cast<float2*>(&v);
    }
}

extern "C" void kernel_launch(void* const* d_in, const int* in_sizes, int n_in,
                              void* d_out, int out_size) {
    const float* noise = (const float*)d_in[0];     // (1024, 10)
    const float* qp    = (const float*)d_in[1];     // (4, 6, 10)
    float* out = (float*)d_out;                     // (1024, 40)

    // 4096 circuits, one warp each; 2 warps/block -> 2048 blocks
    sim_kernel<<<(BATCH * NGEN) / 2, 64>>>(noise, qp, out);
}

// round 9
// speedup vs baseline: 1.0111x; 1.0111x over previous
#include <cuda_runtime.h>

#define NQ 10
#define NGEN 4
#define QD 6
#define BATCH 1024

typedef unsigned long long ull;

// ---- packed f32x2 helpers (re in lo, im in hi) ----
__device__ __forceinline__ ull pk(float lo, float hi) {
    ull r; asm("mov.b64 %0, {%1, %2};" : "=l"(r) : "f"(lo), "f"(hi)); return r;
}
__device__ __forceinline__ void upk(ull v, float& lo, float& hi) {
    asm("mov.b64 {%0, %1}, %2;" : "=f"(lo), "=f"(hi) : "l"(v));
}
__device__ __forceinline__ ull fma2(ull a, ull b, ull c) {
    ull d; asm("fma.rn.f32x2 %0, %1, %2, %3;" : "=l"(d) : "l"(a), "l"(b), "l"(c)); return d;
}
__device__ __forceinline__ ull mul2(ull a, ull b) {
    ull d; asm("mul.rn.f32x2 %0, %1, %2;" : "=l"(d) : "l"(a), "l"(b)); return d;
}

// One warp per (batch, gen) circuit. Amp index i (10 bits): lane = bits 9..5,
// register index r = bits 4..0. PennyLane wire q <-> bit (9-q).
__global__ void __launch_bounds__(64, 12) sim_kernel(const float* __restrict__ noise,
                                                     const float* __restrict__ qp,
                                                     float* __restrict__ out) {
    const unsigned FULL = 0xffffffffu;
    int gwarp = blockIdx.x * 2 + (threadIdx.x >> 5);
    int lane  = threadIdx.x & 31;
    int batch = gwarp >> 2;
    int gen   = gwarp & 3;

    ull S[32];  // packed (re, im) per amplitude

    // ---- in-warp angle prep for init ----
    // lanes 0..9: sincos(noise[batch,q]/2); lanes 16..25: sincos(w[gen,0,q]/2)
    float c_my = 0.f, s_my = 0.f;
    {
        float ang = 0.f;
        if (lane < NQ)                 ang = noise[batch * NQ + lane];
        else if (lane >= 16 && lane < 16 + NQ)
                                       ang = qp[(gen * QD + 0) * NQ + (lane - 16)];
        sincosf(0.5f * ang, &s_my, &c_my);
    }

    // Per-wire init vector: u = RX(n)RY(n)|0> = (C^2 - i S^2, CS - i CS),
    // then layer-0 RY(w):  v = RY(w) u
    auto wire_vec = [&](int q, float& v0r, float& v0i, float& v1r, float& v1i) {
        float C  = __shfl_sync(FULL, c_my, q);
        float Sn = __shfl_sync(FULL, s_my, q);
        float wc = __shfl_sync(FULL, c_my, 16 + q);
        float ws = __shfl_sync(FULL, s_my, 16 + q);
        float u0r = C * C, u0i = -Sn * Sn;
        float u1r = C * Sn, u1i = -(C * Sn);
        v0r = wc * u0r - ws * u1r;  v0i = wc * u0i - ws * u1i;
        v1r = ws * u0r + wc * u1r;  v1i = ws * u0i + wc * u1i;
    };

    // laneF = prod over wires 0..4 of v_w[bit], bit = (lane >> (4-w)) & 1
    float fr = 1.0f, fi = 0.0f;
    #pragma unroll
    for (int w = 0; w < 5; ++w) {
        float v0r, v0i, v1r, v1i;
        wire_vec(w, v0r, v0i, v1r, v1i);
        int bit = (lane >> (4 - w)) & 1;
        float pr = bit ? v1r : v0r;
        float pi = bit ? v1i : v0i;
        float nr = fr * pr - fi * pi;
        float ni = fr * pi + fi * pr;
        fr = nr; fi = ni;
    }

    // Build local 32-amp product table over wires 9..5 (bits 0..4 of r)
    S[0] = pk(fr, fi);
    #pragma unroll
    for (int k = 0; k < 5; ++k) {
        int w = 9 - k;
        int len = 1 << k;
        float v0r, v0i, v1r, v1i;
        wire_vec(w, v0r, v0i, v1r, v1i);
        #pragma unroll
        for (int r = 0; r < (1 << k); ++r) {
            float ar, ai; upk(S[r], ar, ai);
            S[r]       = pk(ar * v0r - ai * v0i, ar * v0i + ai * v0r);
            S[r + len] = pk(ar * v1r - ai * v1i, ar * v1i + ai * v1r);
        }
    }

    // CZ-chain sign mask: bit r of M = K(r) ^ p_lane ^ ((lane&1) & (r>>4))
    unsigned K = 0;
    #pragma unroll
    for (int r = 0; r < 32; ++r)
        K |= (unsigned)(__popc(r & (r >> 1)) & 1) << r;   // compile-time constant
    unsigned p_lane = __popc(lane & (lane >> 1)) & 1u;
    unsigned M = K ^ (p_lane ? 0xFFFFFFFFu : 0u) ^ ((lane & 1) ? 0xFFFF0000u : 0u);

    auto apply_cz = [&]() {
        #pragma unroll
        for (int r = 0; r < 32; ++r) {
            ull sg = ((M >> r) & 1u) ? 0x8000000080000000ull : 0ull;
            S[r] ^= sg;
        }
    };

    apply_cz();  // layer 0's CZ (layer-0 RY fused into init)

    #pragma unroll 1
    for (int l = 1; l < QD; ++l) {
        // lanes 0..9 compute this layer's sincos; also the shear tan
        float lc = 0.f, ls = 0.f, lt = 0.f;
        if (lane < NQ) {
            float ang = qp[(gen * QD + l) * NQ + lane];
            sincosf(0.5f * ang, &ls, &lc);
            lt = __fdividef(ls, 1.0f + lc);   // tan(ang/4)
        }

        // register-bit gates first (wires 5..9), 3-shear form
        #pragma unroll
        for (int q = 5; q < NQ; ++q) {
            const int m = 1 << (9 - q);
            float t = __shfl_sync(FULL, lt, q);
            float s = __shfl_sync(FULL, ls, q);
            ull tn = pk(-t, -t);
            ull ss = pk(s, s);
            #pragma unroll
            for (int r = 0; r < 32; ++r) {
                if (r & m) continue;
                int r1 = r | m;
                ull u   = fma2(tn, S[r1], S[r]);   // a0 - t a1
                ull a1p = fma2(ss, u, S[r1]);      // a1 + s u
                S[r]  = fma2(tn, a1p, u);          // u - t a1'
                S[r1] = a1p;
            }
        }

        // lane-bit gates (wires 0..4)
        #pragma unroll
        for (int q = 0; q < 5; ++q) {
            int lb = 4 - q;
            float c = __shfl_sync(FULL, lc, q);
            float s = __shfl_sync(FULL, ls, q);
            float ssn = ((lane >> lb) & 1) ? s : -s;
            ull cc = pk(c, c);
            ull s2 = pk(ssn, ssn);
            #pragma unroll
            for (int r = 0; r < 32; ++r) {
                ull p = __shfl_xor_sync(FULL, S[r], 1 << lb);
                S[r] = fma2(cc, S[r], mul2(s2, p));
            }
        }

        apply_cz();
    }

    // Expectations: <X_q> = sum_i Re(conj(a_i) * a_{i ^ bit(9-q)})
    // Fused per-pair: compute 2 wires, reduce, store — keeps live regs low.
    int obase = batch * (NGEN * NQ) + gen * NQ;
    #pragma unroll
    for (int k = 0; k < 5; ++k) {
        float a2[2];
        #pragma unroll
        for (int j = 0; j < 2; ++j) {
            int q = 2 * k + j;
            float a = 0.0f;
            if (q < 5) {
                int lb = 4 - q;
                #pragma unroll
                for (int r = 0; r < 32; ++r) {
                    ull p = __shfl_xor_sync(FULL, S[r], 1 << lb);
                    float re, im, pre, pim;
                    upk(S[r], re, im); upk(p, pre, pim);
                    a = fmaf(re, pre, a);
                    a = fmaf(im, pim, a);
                }
            } else {
                const int m = 1 << (9 - q);
                #pragma unroll
                for (int r = 0; r < 32; ++r) {
                    float re, im, pre, pim;
                    upk(S[r], re, im); upk(S[r ^ m], pre, pim);
                    a = fmaf(re, pre, a);
                    a = fmaf(im, pim, a);
                }
            }
            a2[j] = a;
        }
        ull v = pk(a2[0], a2[1]);
        #pragma unroll
        for (int o = 16; o > 0; o >>= 1) {
            ull p = __shfl_xor_sync(FULL, v, o);
            asm("add.rn.f32x2 %0, %1, %2;" : "=l"(v) : "l"(v), "l"(p));
        }
        if (lane == 0)
            *reinterpret_cast<float2*>(out + obase + 2 * k) =
                *reinterpret_cast<float2*>(&v);
    }
}

extern "C" void kernel_launch(void* const* d_in, const int* in_sizes, int n_in,
                              void* d_out, int out_size) {
    const float* noise = (const float*)d_in[0];     // (1024, 10)
    const float* qp    = (const float*)d_in[1];     // (4, 6, 10)
    float* out = (float*)d_out;                     // (1024, 40)

    // 4096 circuits, one warp each; 2 warps/block -> 2048 blocks
    sim_kernel<<<(BATCH * NGEN) / 2, 64>>>(noise, qp, out);
}

// round 10
// speedup vs baseline: 1.2251x; 1.2117x over previous
#include <cuda_runtime.h>

#define NQ 10
#define NGEN 4
#define QD 6
#define BATCH 1024

typedef unsigned long long ull;

// ---- packed f32x2 helpers (re in lo, im in hi) ----
__device__ __forceinline__ ull pk(float lo, float hi) {
    ull r; asm("mov.b64 %0, {%1, %2};" : "=l"(r) : "f"(lo), "f"(hi)); return r;
}
__device__ __forceinline__ void upk(ull v, float& lo, float& hi) {
    asm("mov.b64 {%0, %1}, %2;" : "=f"(lo), "=f"(hi) : "l"(v));
}
__device__ __forceinline__ ull fma2(ull a, ull b, ull c) {
    ull d; asm("fma.rn.f32x2 %0, %1, %2, %3;" : "=l"(d) : "l"(a), "l"(b), "l"(c)); return d;
}
__device__ __forceinline__ ull mul2(ull a, ull b) {
    ull d; asm("mul.rn.f32x2 %0, %1, %2;" : "=l"(d) : "l"(a), "l"(b)); return d;
}

// One 64-thread block per (batch, gen) circuit.
// Amp index i (10 bits): bit9 = warp bit W, bits 8..4 = lane bits 4..0,
// bits 3..0 = register bits 3..0.  PennyLane wire q <-> bit (9-q):
//   wire 0 -> W (smem exchange), wires 1..5 -> lane bit (5-q) (shfl),
//   wires 6..9 -> reg bit (9-q) (register pairs).
__global__ void __launch_bounds__(64, 14) sim_kernel(const float* __restrict__ noise,
                                                     const float* __restrict__ qp,
                                                     float* __restrict__ out) {
    __shared__ ull xch[16 * 64];   // exchange buffer: xch[r*64 + tid], 8KB

    const unsigned FULL = 0xffffffffu;
    int tid  = threadIdx.x;
    int lane = tid & 31;
    int W    = tid >> 5;
    int batch = blockIdx.x >> 2;
    int gen   = blockIdx.x & 3;

    ull S[16];  // packed (re, im) per amplitude

    // ---- in-warp angle prep (both warps compute identically) ----
    // lanes 0..9: sincos(noise[batch,q]/2); lanes 16..25: sincos(w[gen,0,q]/2)
    float c_my = 0.f, s_my = 0.f;
    {
        float ang = 0.f;
        if (lane < NQ)                 ang = noise[batch * NQ + lane];
        else if (lane >= 16 && lane < 16 + NQ)
                                       ang = qp[(gen * QD + 0) * NQ + (lane - 16)];
        sincosf(0.5f * ang, &s_my, &c_my);
    }

    // Per-wire init vector: u = RX(n)RY(n)|0> = (C^2 - i S^2, CS - i CS),
    // then layer-0 RY(w):  v = RY(w) u
    auto wire_vec = [&](int q, float& v0r, float& v0i, float& v1r, float& v1i) {
        float C  = __shfl_sync(FULL, c_my, q);
        float Sn = __shfl_sync(FULL, s_my, q);
        float wc = __shfl_sync(FULL, c_my, 16 + q);
        float ws = __shfl_sync(FULL, s_my, 16 + q);
        float u0r = C * C, u0i = -Sn * Sn;
        float u1r = C * Sn, u1i = -(C * Sn);
        v0r = wc * u0r - ws * u1r;  v0i = wc * u0i - ws * u1i;
        v1r = ws * u0r + wc * u1r;  v1i = ws * u0i + wc * u1i;
    };

    // thread factor = prod over wires 0..5 of v_w[bit]
    float fr = 1.0f, fi = 0.0f;
    #pragma unroll
    for (int w = 0; w < 6; ++w) {
        float v0r, v0i, v1r, v1i;
        wire_vec(w, v0r, v0i, v1r, v1i);
        int bit = (w == 0) ? W : ((lane >> (5 - w)) & 1);
        float pr = bit ? v1r : v0r;
        float pi = bit ? v1i : v0i;
        float nr = fr * pr - fi * pi;
        float ni = fr * pi + fi * pr;
        fr = nr; fi = ni;
    }

    // Build local 16-amp product table over wires 9..6 (reg bits 0..3)
    S[0] = pk(fr, fi);
    #pragma unroll
    for (int k = 0; k < 4; ++k) {
        int w = 9 - k;
        int len = 1 << k;
        float v0r, v0i, v1r, v1i;
        wire_vec(w, v0r, v0i, v1r, v1i);
        #pragma unroll
        for (int r = 0; r < (1 << k); ++r) {
            float ar, ai; upk(S[r], ar, ai);
            S[r]       = pk(ar * v0r - ai * v0i, ar * v0i + ai * v0r);
            S[r + len] = pk(ar * v1r - ai * v1i, ar * v1i + ai * v1r);
        }
    }

    // CZ-chain sign mask over r (16 bits). With i = (W<<9)|(lane<<4)|r:
    //   parity = par(r&(r>>1)) ^ (r3 & lane0) ^ par(lane&(lane>>1)&0xF) ^ (lane4 & W)
    unsigned K16 = 0;
    #pragma unroll
    for (int r = 0; r < 16; ++r)
        K16 |= (unsigned)(__popc(r & (r >> 1)) & 1) << r;   // compile-time constant
    unsigned p_hi = ((unsigned)__popc(lane & (lane >> 1) & 0xF) & 1u)
                  ^ (((unsigned)(lane >> 4) & 1u) & (unsigned)W);
    unsigned M = K16 ^ ((lane & 1) ? 0xFF00u : 0u) ^ (p_hi ? 0xFFFFu : 0u);

    auto apply_cz = [&]() {
        #pragma unroll
        for (int r = 0; r < 16; ++r) {
            ull sg = ((M >> r) & 1u) ? 0x8000000080000000ull : 0ull;
            S[r] ^= sg;
        }
    };

    apply_cz();  // layer 0's CZ (layer-0 RY fused into init)

    #pragma unroll 1
    for (int l = 1; l < QD; ++l) {
        // lanes 0..9 compute this layer's sincos + shear tan (both warps)
        float lc = 0.f, ls = 0.f, lt = 0.f;
        if (lane < NQ) {
            float ang = qp[(gen * QD + l) * NQ + lane];
            sincosf(0.5f * ang, &ls, &lc);
            lt = __fdividef(ls, 1.0f + lc);   // tan(ang/4)
        }

        // register-bit gates (wires 6..9), 3-shear form
        #pragma unroll
        for (int q = 6; q < NQ; ++q) {
            const int m = 1 << (9 - q);
            float t = __shfl_sync(FULL, lt, q);
            float s = __shfl_sync(FULL, ls, q);
            ull tn = pk(-t, -t);
            ull ss = pk(s, s);
            #pragma unroll
            for (int r = 0; r < 16; ++r) {
                if (r & m) continue;
                int r1 = r | m;
                ull u   = fma2(tn, S[r1], S[r]);   // a0 - t a1
                ull a1p = fma2(ss, u, S[r1]);      // a1 + s u
                S[r]  = fma2(tn, a1p, u);          // u - t a1'
                S[r1] = a1p;
            }
        }

        // lane-bit gates (wires 1..5)
        #pragma unroll
        for (int q = 1; q < 6; ++q) {
            int lb = 5 - q;
            float c = __shfl_sync(FULL, lc, q);
            float s = __shfl_sync(FULL, ls, q);
            float ssn = ((lane >> lb) & 1) ? s : -s;
            ull cc = pk(c, c);
            ull s2 = pk(ssn, ssn);
            #pragma unroll
            for (int r = 0; r < 16; ++r) {
                ull p = __shfl_xor_sync(FULL, S[r], 1 << lb);
                S[r] = fma2(cc, S[r], mul2(s2, p));
            }
        }

        // warp-bit gate (wire 0): exchange with partner thread in other warp
        {
            float c = __shfl_sync(FULL, lc, 0);
            float s = __shfl_sync(FULL, ls, 0);
            float ssn = W ? s : -s;
            ull cc = pk(c, c);
            ull s2 = pk(ssn, ssn);
            #pragma unroll
            for (int r = 0; r < 16; ++r) xch[r * 64 + tid] = S[r];
            __syncthreads();
            #pragma unroll
            for (int r = 0; r < 16; ++r) {
                ull p = xch[r * 64 + (tid ^ 32)];
                S[r] = fma2(cc, S[r], mul2(s2, p));
            }
            __syncthreads();
        }

        apply_cz();
    }

    // Expectations: <X_q> = sum_i Re(conj(a_i) * a_{i ^ bit(9-q)})
    float acc[NQ];

    // q = 0: warp-bit partner dot via smem exchange
    {
        #pragma unroll
        for (int r = 0; r < 16; ++r) xch[r * 64 + tid] = S[r];
        __syncthreads();
        float a = 0.0f;
        #pragma unroll
        for (int r = 0; r < 16; ++r) {
            ull p = xch[r * 64 + (tid ^ 32)];
            float re, im, pre, pim;
            upk(S[r], re, im); upk(p, pre, pim);
            a = fmaf(re, pre, a);
            a = fmaf(im, pim, a);
        }
        acc[0] = a;
        __syncthreads();   // xch free for reduction reuse below
    }

    // q = 1..5: lane-bit partner via shuffle
    #pragma unroll
    for (int q = 1; q < 6; ++q) {
        int lb = 5 - q;
        float a = 0.0f;
        #pragma unroll
        for (int r = 0; r < 16; ++r) {
            ull p = __shfl_xor_sync(FULL, S[r], 1 << lb);
            float re, im, pre, pim;
            upk(S[r], re, im); upk(p, pre, pim);
            a = fmaf(re, pre, a);
            a = fmaf(im, pim, a);
        }
        acc[q] = a;
    }

    // q = 6..9: register-bit partner, purely local
    #pragma unroll
    for (int q = 6; q < NQ; ++q) {
        const int m = 1 << (9 - q);
        float a = 0.0f;
        #pragma unroll
        for (int r = 0; r < 16; ++r) {
            float re, im, pre, pim;
            upk(S[r], re, im); upk(S[r ^ m], pre, pim);
            a = fmaf(re, pre, a);
            a = fmaf(im, pim, a);
        }
        acc[q] = a;
    }

    // per-warp packed butterfly reduction (5 ull accumulators)
    ull vk[5];
    #pragma unroll
    for (int k = 0; k < 5; ++k) {
        ull v = pk(acc[2 * k], acc[2 * k + 1]);
        #pragma unroll
        for (int o = 16; o > 0; o >>= 1) {
            ull p = __shfl_xor_sync(FULL, v, o);
            asm("add.rn.f32x2 %0, %1, %2;" : "=l"(v) : "l"(v), "l"(p));
        }
        vk[k] = v;
    }

    // cross-warp combine via smem, then store 10 floats
    if (tid == 32) {
        #pragma unroll
        for (int k = 0; k < 5; ++k) xch[k] = vk[k];
    }
    __syncthreads();
    if (tid == 0) {
        int obase = blockIdx.x * NQ;
        #pragma unroll
        for (int k = 0; k < 5; ++k) {
            ull v = vk[k], p = xch[k];
            asm("add.rn.f32x2 %0, %1, %2;" : "=l"(v) : "l"(v), "l"(p));
            *reinterpret_cast<float2*>(out + obase + 2 * k) =
                *reinterpret_cast<float2*>(&v);
        }
    }
}

extern "C" void kernel_launch(void* const* d_in, const int* in_sizes, int n_in,
                              void* d_out, int out_size) {
    const float* noise = (const float*)d_in[0];     // (1024, 10)
    const float* qp    = (const float*)d_in[1];     // (4, 6, 10)
    float* out = (float*)d_out;                     // (1024, 40)

    // 4096 circuits, one 64-thread block each
    sim_kernel<<<BATCH * NGEN, 64>>>(noise, qp, out);
}

// round 11
// speedup vs baseline: 1.6194x; 1.3218x over previous
#include <cuda_runtime.h>

#define NQ 10
#define NGEN 4
#define QD 6
#define BATCH 1024

typedef unsigned long long ull;

// ---- packed f32x2 helpers (re in lo, im in hi) ----
__device__ __forceinline__ ull pk(float lo, float hi) {
    ull r; asm("mov.b64 %0, {%1, %2};" : "=l"(r) : "f"(lo), "f"(hi)); return r;
}
__device__ __forceinline__ void upk(ull v, float& lo, float& hi) {
    asm("mov.b64 {%0, %1}, %2;" : "=f"(lo), "=f"(hi) : "l"(v));
}
__device__ __forceinline__ ull fma2(ull a, ull b, ull c) {
    ull d; asm("fma.rn.f32x2 %0, %1, %2, %3;" : "=l"(d) : "l"(a), "l"(b), "l"(c)); return d;
}
__device__ __forceinline__ ull mul2(ull a, ull b) {
    ull d; asm("mul.rn.f32x2 %0, %1, %2;" : "=l"(d) : "l"(a), "l"(b)); return d;
}

// One warp per (batch, gen) circuit. Amp index i (10 bits): lane = bits 9..5,
// register index r = bits 4..0. PennyLane wire q <-> bit (9-q).
__global__ void __launch_bounds__(64, 10) sim_kernel(const float* __restrict__ noise,
                                                     const float* __restrict__ qp,
                                                     float* __restrict__ out) {
    const unsigned FULL = 0xffffffffu;
    int gwarp = blockIdx.x * 2 + (threadIdx.x >> 5);
    int lane  = threadIdx.x & 31;
    int batch = gwarp >> 2;
    int gen   = gwarp & 3;

    ull S[32];  // packed (re, im) per amplitude (scaled by 1/G after layer loop)

    // ---- in-warp angle prep for init ----
    // lanes 0..9: sincos(noise[batch,q]/2); lanes 16..25: sincos(w[gen,0,q]/2)
    float c_my = 0.f, s_my = 0.f;
    {
        float ang = 0.f;
        if (lane < NQ)                 ang = noise[batch * NQ + lane];
        else if (lane >= 16 && lane < 16 + NQ)
                                       ang = qp[(gen * QD + 0) * NQ + (lane - 16)];
        sincosf(0.5f * ang, &s_my, &c_my);
    }

    // Per-wire init vector: u = RX(n)RY(n)|0> = (C^2 - i S^2, CS - i CS),
    // then layer-0 RY(w):  v = RY(w) u   (exact, unscaled)
    auto wire_vec = [&](int q, float& v0r, float& v0i, float& v1r, float& v1i) {
        float C  = __shfl_sync(FULL, c_my, q);
        float Sn = __shfl_sync(FULL, s_my, q);
        float wc = __shfl_sync(FULL, c_my, 16 + q);
        float ws = __shfl_sync(FULL, s_my, 16 + q);
        float u0r = C * C, u0i = -Sn * Sn;
        float u1r = C * Sn, u1i = -(C * Sn);
        v0r = wc * u0r - ws * u1r;  v0i = wc * u0i - ws * u1i;
        v1r = ws * u0r + wc * u1r;  v1i = ws * u0i + wc * u1i;
    };

    // laneF = prod over wires 0..4 of v_w[bit], bit = (lane >> (4-w)) & 1
    float fr = 1.0f, fi = 0.0f;
    #pragma unroll
    for (int w = 0; w < 5; ++w) {
        float v0r, v0i, v1r, v1i;
        wire_vec(w, v0r, v0i, v1r, v1i);
        int bit = (lane >> (4 - w)) & 1;
        float pr = bit ? v1r : v0r;
        float pi = bit ? v1i : v0i;
        float nr = fr * pr - fi * pi;
        float ni = fr * pi + fi * pr;
        fr = nr; fi = ni;
    }

    // Build local 32-amp product table over wires 9..5 (bits 0..4 of r)
    S[0] = pk(fr, fi);
    #pragma unroll
    for (int k = 0; k < 5; ++k) {
        int w = 9 - k;
        int len = 1 << k;
        float v0r, v0i, v1r, v1i;
        wire_vec(w, v0r, v0i, v1r, v1i);
        #pragma unroll
        for (int r = 0; r < (1 << k); ++r) {
            float ar, ai; upk(S[r], ar, ai);
            S[r]       = pk(ar * v0r - ai * v0i, ar * v0i + ai * v0r);
            S[r + len] = pk(ar * v1r - ai * v1i, ar * v1i + ai * v1r);
        }
    }

    // CZ-chain sign mask: bit r of M = K(r) ^ p_lane ^ ((lane&1) & (r>>4))
    unsigned K = 0;
    #pragma unroll
    for (int r = 0; r < 32; ++r)
        K |= (unsigned)(__popc(r & (r >> 1)) & 1) << r;   // compile-time constant
    unsigned p_lane = __popc(lane & (lane >> 1)) & 1u;
    unsigned M = K ^ (p_lane ? 0xFFFFFFFFu : 0u) ^ ((lane & 1) ? 0xFFFF0000u : 0u);

    auto apply_cz = [&]() {
        #pragma unroll
        for (int r = 0; r < 32; ++r) {
            ull sg = ((M >> r) & 1u) ? 0x8000000080000000ull : 0ull;
            S[r] ^= sg;
        }
    };

    apply_cz();  // layer 0's CZ (layer-0 RY fused into init)

    float Gtot = 1.0f;  // product of all factored-out cos(ang/2)

    #pragma unroll 1
    for (int l = 1; l < QD; ++l) {
        // lanes 0..9: this layer's cos and t = tan(ang/2); others: cos = 1
        float lc = 1.0f, lt = 0.0f;
        if (lane < NQ) {
            float ang = qp[(gen * QD + l) * NQ + lane];
            float ls;
            sincosf(0.5f * ang, &ls, &lc);
            lt = __fdividef(ls, lc);          // tan(ang/2)
        }
        // accumulate the 10 cos factors (butterfly product; inactive lanes = 1)
        {
            float g = lc;
            #pragma unroll
            for (int o = 16; o > 0; o >>= 1)
                g *= __shfl_xor_sync(FULL, g, o);
            Gtot *= g;
        }

        // register-bit gates (wires 5..9): scaled RY = (a0 - t a1, t a0 + a1)
        #pragma unroll
        for (int q = 5; q < NQ; ++q) {
            const int m = 1 << (9 - q);
            float t = __shfl_sync(FULL, lt, q);
            ull tp = pk(t, t);
            ull tn = pk(-t, -t);
            #pragma unroll
            for (int r = 0; r < 32; ++r) {
                if (r & m) continue;
                int r1 = r | m;
                ull a0 = S[r], a1 = S[r1];
                S[r]  = fma2(tn, a1, a0);
                S[r1] = fma2(tp, a0, a1);
            }
        }

        // lane-bit gates (wires 0..4): S += (+-t) * partner
        #pragma unroll
        for (int q = 0; q < 5; ++q) {
            int lb = 4 - q;
            float t = __shfl_sync(FULL, lt, q);
            float tsgn = ((lane >> lb) & 1) ? t : -t;
            ull T = pk(tsgn, tsgn);
            #pragma unroll
            for (int r = 0; r < 32; ++r) {
                ull p = __shfl_xor_sync(FULL, S[r], 1 << lb);
                S[r] = fma2(T, p, S[r]);
            }
        }

        apply_cz();
    }

    // Expectations: <X_q> = G^2 * sum_i Re(conj(a_i) * a_{i ^ bit(9-q)})
    float acc[NQ];
    #pragma unroll
    for (int q = 0; q < NQ; ++q) {
        float a = 0.0f;
        if (q < 5) {
            int lb = 4 - q;
            #pragma unroll
            for (int r = 0; r < 32; ++r) {
                ull p = __shfl_xor_sync(FULL, S[r], 1 << lb);
                float re, im, pre, pim;
                upk(S[r], re, im); upk(p, pre, pim);
                a = fmaf(re, pre, a);
                a = fmaf(im, pim, a);
            }
        } else {
            const int m = 1 << (9 - q);
            #pragma unroll
            for (int r = 0; r < 32; ++r) {
                float re, im, pre, pim;
                upk(S[r], re, im); upk(S[r ^ m], pre, pim);
                a = fmaf(re, pre, a);
                a = fmaf(im, pim, a);
            }
        }
        acc[q] = a;
    }

    // packed pairwise butterfly reduction, then scale by G^2 and store
    float G2 = Gtot * Gtot;
    ull G2p = pk(G2, G2);
    int obase = batch * (NGEN * NQ) + gen * NQ;
    #pragma unroll
    for (int k = 0; k < 5; ++k) {
        ull v = pk(acc[2 * k], acc[2 * k + 1]);
        #pragma unroll
        for (int o = 16; o > 0; o >>= 1) {
            ull p = __shfl_xor_sync(FULL, v, o);
            asm("add.rn.f32x2 %0, %1, %2;" : "=l"(v) : "l"(v), "l"(p));
        }
        if (lane == 0) {
            v = mul2(v, G2p);
            *reinterpret_cast<float2*>(out + obase + 2 * k) =
                *reinterpret_cast<float2*>(&v);
        }
    }
}

extern "C" void kernel_launch(void* const* d_in, const int* in_sizes, int n_in,
                              void* d_out, int out_size) {
    const float* noise = (const float*)d_in[0];     // (1024, 10)
    const float* qp    = (const float*)d_in[1];     // (4, 6, 10)
    float* out = (float*)d_out;                     // (1024, 40)

    // 4096 circuits, one warp each; 2 warps/block -> 2048 blocks
    sim_kernel<<<(BATCH * NGEN) / 2, 64>>>(noise, qp, out);
}